// round 1
// baseline (speedup 1.0000x reference)
#include <cuda_runtime.h>
#include <math.h>

#define N_NODES 50000
#define N_EDGES 1600000
#define BATCH   2
#define C       64

// ---- scratch (no allocations allowed; __device__ globals are the sanctioned path) ----
__device__ float g_deg[N_NODES];
__device__ float g_dis[N_NODES];
__device__ float g_xc[(size_t)BATCH * N_NODES * C];
__device__ float g_xd[(size_t)BATCH * N_NODES * C];
__device__ int   g_is64;

// ---------------------------------------------------------------------------
// Detect whether edge_index is int64 or int32.
// If int64 (values < 2^31, nonnegative), every odd 32-bit word is 0.
// If int32, sampled words are random node ids in [0, 50000) -> OR != 0
// with overwhelming probability over 4096 samples.
// Deterministic, device-only, graph-capturable.
// ---------------------------------------------------------------------------
__global__ void detect_kernel(const unsigned int* __restrict__ w) {
    __shared__ unsigned int acc;
    if (threadIdx.x == 0) acc = 0u;
    __syncthreads();
    unsigned int v = 0u;
    for (int i = threadIdx.x; i < 4096; i += blockDim.x) {
        // odd word positions, strided through the first ~800K words
        v |= w[(size_t)2 * i * 97 + 1];
    }
    atomicOr(&acc, v);
    __syncthreads();
    if (threadIdx.x == 0) g_is64 = (acc == 0u) ? 1 : 0;
}

// ---------------------------------------------------------------------------
// Degree: init with self-loop (deg = 1), histogram target indices.
// ---------------------------------------------------------------------------
__global__ void deg_init_kernel() {
    int i = blockIdx.x * blockDim.x + threadIdx.x;
    if (i < N_NODES) g_deg[i] = 1.0f;
}

__global__ void hist_kernel(const long long* __restrict__ ei64,
                            const int* __restrict__ ei32) {
    int e = blockIdx.x * blockDim.x + threadIdx.x;
    if (e >= N_EDGES) return;
    int t = g_is64 ? (int)ei64[(size_t)N_EDGES + e] : ei32[(size_t)N_EDGES + e];
    atomicAdd(&g_deg[t], 1.0f);
}

__global__ void dis_kernel() {
    int i = blockIdx.x * blockDim.x + threadIdx.x;
    if (i < N_NODES) g_dis[i] = rsqrtf(g_deg[i]);   // deg >= 1 always (self-loop)
}

// ---------------------------------------------------------------------------
// Fused dual GEMM + self-loop + bias:
//   xc[m,o] = sum_k x[m,k] * Wc[o,k]
//   xd[m,o] = sum_k x[m,k] * Wd[o,k]
//   out[m,o] = bias[o] + (1/deg[n]) * xc[m,o]      (self-loop, f=0)
// 256 threads: thread (o = tid>>2 in [0,64), kg = tid&3) holds 16-wide K-slices
// of W row o for BOTH matrices in registers. x rows staged in shared (4/iter).
// Quad-lane shfl_xor reduction combines the 4 K-slices.
// ---------------------------------------------------------------------------
__global__ void __launch_bounds__(256)
gemm_selfloop_kernel(const float* __restrict__ x,
                     const float* __restrict__ Wc,
                     const float* __restrict__ Wd,
                     const float* __restrict__ bias,
                     float* __restrict__ out) {
    const int o  = threadIdx.x >> 2;   // output channel 0..63
    const int kg = threadIdx.x & 3;    // k-group 0..3 (16 k each)

    float wc[16], wd[16];
#pragma unroll
    for (int i = 0; i < 16; i++) {
        wc[i] = Wc[o * C + kg * 16 + i];
        wd[i] = Wd[o * C + kg * 16 + i];
    }
    const float bo = bias[o];

    __shared__ __align__(16) float xs[4][C];

    const int M = BATCH * N_NODES;          // 100000, divisible by 4
    const int lr = threadIdx.x >> 6;        // row-in-tile for loading
    const int lc = threadIdx.x & 63;        // col for loading

    for (int m0 = blockIdx.x * 4; m0 < M; m0 += gridDim.x * 4) {
        __syncthreads();
        xs[lr][lc] = x[(size_t)(m0 + lr) * C + lc];
        __syncthreads();

#pragma unroll
        for (int r2 = 0; r2 < 4; r2++) {
            const float4* xp = (const float4*)&xs[r2][kg * 16];
            float sc = 0.0f, sd = 0.0f;
#pragma unroll
            for (int j = 0; j < 4; j++) {
                float4 xv = xp[j];
                sc = fmaf(wc[4 * j + 0], xv.x, sc);
                sc = fmaf(wc[4 * j + 1], xv.y, sc);
                sc = fmaf(wc[4 * j + 2], xv.z, sc);
                sc = fmaf(wc[4 * j + 3], xv.w, sc);
                sd = fmaf(wd[4 * j + 0], xv.x, sd);
                sd = fmaf(wd[4 * j + 1], xv.y, sd);
                sd = fmaf(wd[4 * j + 2], xv.z, sd);
                sd = fmaf(wd[4 * j + 3], xv.w, sd);
            }
            // reduce the 4 k-groups (lanes 4q..4q+3 share o)
            sc += __shfl_xor_sync(0xffffffffu, sc, 1);
            sc += __shfl_xor_sync(0xffffffffu, sc, 2);
            sd += __shfl_xor_sync(0xffffffffu, sd, 1);
            sd += __shfl_xor_sync(0xffffffffu, sd, 2);

            if (kg == 0) {
                const int m = m0 + r2;
                const size_t idx = (size_t)m * C + o;
                g_xc[idx] = sc;
                g_xd[idx] = sd;
                const int n = (m >= N_NODES) ? (m - N_NODES) : m;
                const float dv = g_dis[n];
                out[idx] = bo + dv * dv * sc;   // self-loop: norm = 1/deg, f = 0
            }
        }
    }
}

// ---------------------------------------------------------------------------
// Edge kernel: one warp per edge, both batches at once.
//   lane: b = lane>>4, channels [4*(lane&15), +4)
//   msg = norm * ((1-f)*xc[src] + f*xd[src]) ; red.v4.f32 into out[tgt]
// ---------------------------------------------------------------------------
__global__ void __launch_bounds__(256)
edge_kernel(const long long* __restrict__ ei64,
            const int* __restrict__ ei32,
            const float* __restrict__ fdo,
            const float* __restrict__ fluxes,
            float* __restrict__ out) {
    const int gw = (int)((blockIdx.x * blockDim.x + threadIdx.x) >> 5);
    if (gw >= N_EDGES) return;
    const int lane = threadIdx.x & 31;

    int s, t;
    if (g_is64) {
        s = (int)ei64[gw];
        t = (int)ei64[(size_t)N_EDGES + gw];
    } else {
        s = ei32[gw];
        t = ei32[(size_t)N_EDGES + gw];
    }

    const float norm = g_dis[s] * g_dis[t];
    const float f0   = fdo[gw];

    const int b  = lane >> 4;
    const int c4 = (lane & 15) << 2;

    const float fs = fluxes[b * N_NODES + s];
    const float ft = fluxes[b * N_NODES + t];
    const float keep = 0.5f * (1.0f + tanhf(fs * ft));   // TEMPERATURE = 1
    const float f  = keep * f0 + (1.0f - keep) * (1.0f - f0);
    const float cC = norm * (1.0f - f);
    const float cD = norm * f;

    const size_t sbase = ((size_t)b * N_NODES + s) * C + c4;
    const float4 a = *(const float4*)(g_xc + sbase);
    const float4 d = *(const float4*)(g_xd + sbase);

    float4 m;
    m.x = fmaf(cC, a.x, cD * d.x);
    m.y = fmaf(cC, a.y, cD * d.y);
    m.z = fmaf(cC, a.z, cD * d.z);
    m.w = fmaf(cC, a.w, cD * d.w);

    float* dst = out + ((size_t)b * N_NODES + t) * C + c4;
    asm volatile("red.global.add.v4.f32 [%0], {%1,%2,%3,%4};"
                 :: "l"(dst), "f"(m.x), "f"(m.y), "f"(m.z), "f"(m.w)
                 : "memory");
}

// ---------------------------------------------------------------------------
extern "C" void kernel_launch(void* const* d_in, const int* in_sizes, int n_in,
                              void* d_out, int out_size) {
    const float* x    = (const float*)d_in[0];
    const void*  ei   = d_in[1];                 // int64 or int32, sniffed on device
    const float* fdo  = (const float*)d_in[2];
    const float* flux = (const float*)d_in[3];
    const float* Wc   = (const float*)d_in[4];
    const float* Wd   = (const float*)d_in[5];
    const float* bias = (const float*)d_in[6];
    float* out = (float*)d_out;

    const long long* ei64 = (const long long*)ei;
    const int*       ei32 = (const int*)ei;

    detect_kernel<<<1, 256>>>((const unsigned int*)ei);
    deg_init_kernel<<<(N_NODES + 255) / 256, 256>>>();
    hist_kernel<<<(N_EDGES + 255) / 256, 256>>>(ei64, ei32);
    dis_kernel<<<(N_NODES + 255) / 256, 256>>>();
    gemm_selfloop_kernel<<<2960, 256>>>(x, Wc, Wd, bias, out);
    edge_kernel<<<N_EDGES / 8, 256>>>(ei64, ei32, fdo, flux, out);
}

// round 2
// speedup vs baseline: 1.1229x; 1.1229x over previous
#include <cuda_runtime.h>
#include <math.h>

#define N_NODES 50000
#define N_EDGES 1600000
#define BATCH   2
#define C       64
#define NBLK    ((N_NODES + 255) / 256)   // 196 scan blocks

// ---- scratch (__device__ globals: the sanctioned no-alloc path) ----
__device__ int   g_cnt[N_NODES];
__device__ int   g_off[N_NODES + 1];
__device__ int   g_cursor[N_NODES];
__device__ int   g_bsum[NBLK];
__device__ int   g_bpre[NBLK];
__device__ float g_dis[N_NODES];
__device__ float g_xc[(size_t)BATCH * N_NODES * C];
__device__ float g_xd[(size_t)BATCH * N_NODES * C];
__device__ float4 g_epack[N_EDGES];   // (cC0, cD0, cC1, cD1) per edge
__device__ int    g_esrc[N_EDGES];
__device__ int   g_is64;

// ---------------------------------------------------------------------------
// int64 vs int32 edge_index sniffer (odd words all-zero => int64)
// ---------------------------------------------------------------------------
__global__ void detect_kernel(const unsigned int* __restrict__ w) {
    __shared__ unsigned int acc;
    if (threadIdx.x == 0) acc = 0u;
    __syncthreads();
    unsigned int v = 0u;
    for (int i = threadIdx.x; i < 4096; i += blockDim.x)
        v |= w[(size_t)2 * i * 97 + 1];
    atomicOr(&acc, v);
    __syncthreads();
    if (threadIdx.x == 0) g_is64 = (acc == 0u) ? 1 : 0;
}

__global__ void zero_cnt_kernel() {
    int i = blockIdx.x * blockDim.x + threadIdx.x;
    if (i < N_NODES) g_cnt[i] = 0;
}

__global__ void hist_kernel(const long long* __restrict__ ei64,
                            const int* __restrict__ ei32) {
    int e = blockIdx.x * blockDim.x + threadIdx.x;
    if (e >= N_EDGES) return;
    int t = g_is64 ? (int)ei64[(size_t)N_EDGES + e] : ei32[(size_t)N_EDGES + e];
    atomicAdd(&g_cnt[t], 1);
}

// ---------------------------------------------------------------------------
// Hierarchical exclusive scan of g_cnt -> g_off
// ---------------------------------------------------------------------------
__device__ __forceinline__ int warp_incl_scan(int x) {
#pragma unroll
    for (int d = 1; d < 32; d <<= 1) {
        int y = __shfl_up_sync(0xffffffffu, x, d);
        if ((threadIdx.x & 31) >= d) x += y;
    }
    return x;
}

__global__ void __launch_bounds__(256) scan_local_kernel() {
    int i = blockIdx.x * 256 + threadIdx.x;
    int v = (i < N_NODES) ? g_cnt[i] : 0;
    int lane = threadIdx.x & 31, wid = threadIdx.x >> 5;
    int x = warp_incl_scan(v);
    __shared__ int wsum[8];
    if (lane == 31) wsum[wid] = x;
    __syncthreads();
    if (wid == 0) {
        int s = (lane < 8) ? wsum[lane] : 0;
#pragma unroll
        for (int d = 1; d < 8; d <<= 1) {
            int y = __shfl_up_sync(0xffffffffu, s, d);
            if (lane >= d) s += y;
        }
        if (lane < 8) wsum[lane] = s;
    }
    __syncthreads();
    int incl = x + (wid > 0 ? wsum[wid - 1] : 0);
    if (i < N_NODES) g_off[i] = incl - v;          // local exclusive
    if (threadIdx.x == 255) g_bsum[blockIdx.x] = incl;
}

__global__ void __launch_bounds__(256) scan_block_kernel() {
    int t = threadIdx.x;
    int v = (t < NBLK) ? g_bsum[t] : 0;
    int lane = t & 31, wid = t >> 5;
    int x = warp_incl_scan(v);
    __shared__ int wsum[8];
    if (lane == 31) wsum[wid] = x;
    __syncthreads();
    if (wid == 0) {
        int s = (lane < 8) ? wsum[lane] : 0;
#pragma unroll
        for (int d = 1; d < 8; d <<= 1) {
            int y = __shfl_up_sync(0xffffffffu, s, d);
            if (lane >= d) s += y;
        }
        if (lane < 8) wsum[lane] = s;
    }
    __syncthreads();
    int incl = x + (wid > 0 ? wsum[wid - 1] : 0);
    if (t < NBLK) g_bpre[t] = incl - v;
}

__global__ void finalize_kernel() {
    int i = blockIdx.x * blockDim.x + threadIdx.x;
    if (i < N_NODES) {
        int off = g_off[i] + g_bpre[i >> 8];
        g_off[i] = off;
        g_cursor[i] = off;
        g_dis[i] = rsqrtf((float)(g_cnt[i] + 1));   // +1 self-loop
    }
    if (i == 0) g_off[N_NODES] = N_EDGES;
}

// ---------------------------------------------------------------------------
// Fill CSR buckets; precompute per-(edge,batch) coefficients:
//   pack = (norm*(1-f0'), norm*f0', norm*(1-f1'), norm*f1')
// ---------------------------------------------------------------------------
__global__ void __launch_bounds__(256)
fill_kernel(const long long* __restrict__ ei64,
            const int* __restrict__ ei32,
            const float* __restrict__ fdo,
            const float* __restrict__ fluxes) {
    int e = blockIdx.x * blockDim.x + threadIdx.x;
    if (e >= N_EDGES) return;
    int s, t;
    if (g_is64) { s = (int)ei64[e]; t = (int)ei64[(size_t)N_EDGES + e]; }
    else        { s = ei32[e];      t = ei32[(size_t)N_EDGES + e]; }

    int pos = atomicAdd(&g_cursor[t], 1);

    const float f0   = fdo[e];
    const float norm = g_dis[s] * g_dis[t];

    const float k0 = 0.5f * (1.0f + tanhf(fluxes[s] * fluxes[t]));
    const float k1 = 0.5f * (1.0f + tanhf(fluxes[N_NODES + s] * fluxes[N_NODES + t]));
    const float fb0 = k0 * f0 + (1.0f - k0) * (1.0f - f0);
    const float fb1 = k1 * f0 + (1.0f - k1) * (1.0f - f0);

    g_epack[pos] = make_float4(norm * (1.0f - fb0), norm * fb0,
                               norm * (1.0f - fb1), norm * fb1);
    g_esrc[pos] = s;
}

// ---------------------------------------------------------------------------
// Fused dual GEMM + self-loop + bias (unchanged from R1)
// ---------------------------------------------------------------------------
__global__ void __launch_bounds__(256)
gemm_selfloop_kernel(const float* __restrict__ x,
                     const float* __restrict__ Wc,
                     const float* __restrict__ Wd,
                     const float* __restrict__ bias,
                     float* __restrict__ out) {
    const int o  = threadIdx.x >> 2;
    const int kg = threadIdx.x & 3;

    float wc[16], wd[16];
#pragma unroll
    for (int i = 0; i < 16; i++) {
        wc[i] = Wc[o * C + kg * 16 + i];
        wd[i] = Wd[o * C + kg * 16 + i];
    }
    const float bo = bias[o];

    __shared__ __align__(16) float xs[4][C];
    const int M = BATCH * N_NODES;
    const int lr = threadIdx.x >> 6;
    const int lc = threadIdx.x & 63;

    for (int m0 = blockIdx.x * 4; m0 < M; m0 += gridDim.x * 4) {
        __syncthreads();
        xs[lr][lc] = x[(size_t)(m0 + lr) * C + lc];
        __syncthreads();

#pragma unroll
        for (int r2 = 0; r2 < 4; r2++) {
            const float4* xp = (const float4*)&xs[r2][kg * 16];
            float sc = 0.0f, sd = 0.0f;
#pragma unroll
            for (int j = 0; j < 4; j++) {
                float4 xv = xp[j];
                sc = fmaf(wc[4 * j + 0], xv.x, sc);
                sc = fmaf(wc[4 * j + 1], xv.y, sc);
                sc = fmaf(wc[4 * j + 2], xv.z, sc);
                sc = fmaf(wc[4 * j + 3], xv.w, sc);
                sd = fmaf(wd[4 * j + 0], xv.x, sd);
                sd = fmaf(wd[4 * j + 1], xv.y, sd);
                sd = fmaf(wd[4 * j + 2], xv.z, sd);
                sd = fmaf(wd[4 * j + 3], xv.w, sd);
            }
            sc += __shfl_xor_sync(0xffffffffu, sc, 1);
            sc += __shfl_xor_sync(0xffffffffu, sc, 2);
            sd += __shfl_xor_sync(0xffffffffu, sd, 1);
            sd += __shfl_xor_sync(0xffffffffu, sd, 2);

            if (kg == 0) {
                const int m = m0 + r2;
                const size_t idx = (size_t)m * C + o;
                g_xc[idx] = sc;
                g_xd[idx] = sd;
                const int n = (m >= N_NODES) ? (m - N_NODES) : m;
                const float dv = g_dis[n];
                out[idx] = bo + dv * dv * sc;   // self-loop (f=0, norm=1/deg)
            }
        }
    }
}

// ---------------------------------------------------------------------------
// Gather: one warp per (node, batch). Register accumulation, zero atomics.
// ---------------------------------------------------------------------------
__global__ void __launch_bounds__(256)
gather_kernel(float* __restrict__ out) {
    const int w = (int)((blockIdx.x * blockDim.x + threadIdx.x) >> 5);
    if (w >= 2 * N_NODES) return;
    const int n    = w >> 1;
    const int b    = w & 1;
    const int lane = threadIdx.x & 31;

    const int beg = g_off[n];
    const int end = g_off[n + 1];

    const float* __restrict__ xcb = g_xc + (size_t)b * N_NODES * C;
    const float* __restrict__ xdb = g_xd + (size_t)b * N_NODES * C;

    float ax = 0.0f, ay = 0.0f;

    // 2-stage software pipeline over the bucket
    float4 p; int s;
    if (beg < end) { p = g_epack[beg]; s = g_esrc[beg]; }
    for (int i = beg; i < end; i++) {
        const float4 pc = p;
        const int    sc_ = s;
        if (i + 1 < end) { p = g_epack[i + 1]; s = g_esrc[i + 1]; }

        const float cC = b ? pc.z : pc.x;
        const float cD = b ? pc.w : pc.y;
        const size_t base = (size_t)sc_ * C + 2 * lane;
        const float2 a = *(const float2*)(xcb + base);
        const float2 d = *(const float2*)(xdb + base);
        ax = fmaf(cC, a.x, fmaf(cD, d.x, ax));
        ay = fmaf(cC, a.y, fmaf(cD, d.y, ay));
    }

    const size_t o = ((size_t)b * N_NODES + n) * C + 2 * lane;
    float2 cur = *(float2*)(out + o);     // bias + self-loop from GEMM
    cur.x += ax; cur.y += ay;
    *(float2*)(out + o) = cur;
}

// ---------------------------------------------------------------------------
extern "C" void kernel_launch(void* const* d_in, const int* in_sizes, int n_in,
                              void* d_out, int out_size) {
    const float* x    = (const float*)d_in[0];
    const void*  ei   = d_in[1];
    const float* fdo  = (const float*)d_in[2];
    const float* flux = (const float*)d_in[3];
    const float* Wc   = (const float*)d_in[4];
    const float* Wd   = (const float*)d_in[5];
    const float* bias = (const float*)d_in[6];
    float* out = (float*)d_out;

    const long long* ei64 = (const long long*)ei;
    const int*       ei32 = (const int*)ei;

    detect_kernel<<<1, 256>>>((const unsigned int*)ei);
    zero_cnt_kernel<<<NBLK, 256>>>();
    hist_kernel<<<(N_EDGES + 255) / 256, 256>>>(ei64, ei32);
    scan_local_kernel<<<NBLK, 256>>>();
    scan_block_kernel<<<1, 256>>>();
    finalize_kernel<<<NBLK, 256>>>();
    fill_kernel<<<(N_EDGES + 255) / 256, 256>>>(ei64, ei32, fdo, flux);
    gemm_selfloop_kernel<<<2960, 256>>>(x, Wc, Wd, bias, out);
    gather_kernel<<<(2 * N_NODES * 32 + 255) / 256, 256>>>(out);
}

// round 3
// speedup vs baseline: 1.2009x; 1.0694x over previous
#include <cuda_runtime.h>
#include <math.h>

#define N_NODES 50000
#define N_EDGES 1600000
#define BATCH   2
#define C       64
#define NBLK    ((N_NODES + 255) / 256)   // 196 scan blocks

// ---- scratch (__device__ globals: the sanctioned no-alloc path) ----
__device__ int    g_cnt[N_NODES];
__device__ int    g_off[N_NODES + 1];
__device__ int    g_cursor[N_NODES];
__device__ int    g_bsum[NBLK];
__device__ int    g_bpre[NBLK];
__device__ float  g_dis[N_NODES];
__device__ float  g_xc[(size_t)BATCH * N_NODES * C];
__device__ float  g_xd[(size_t)BATCH * N_NODES * C];
__device__ float2 g_ep0[N_EDGES];     // (cC, cD) for batch 0, CSR order
__device__ float2 g_ep1[N_EDGES];     // (cC, cD) for batch 1, CSR order
__device__ int    g_esrc[N_EDGES];    // src node, CSR order
__device__ int    g_is64;

// ---------------------------------------------------------------------------
// int64 vs int32 sniffer (odd 32-bit words all zero => int64)
// ---------------------------------------------------------------------------
__global__ void detect_kernel(const unsigned int* __restrict__ w) {
    __shared__ unsigned int acc;
    if (threadIdx.x == 0) acc = 0u;
    __syncthreads();
    unsigned int v = 0u;
    for (int i = threadIdx.x; i < 4096; i += blockDim.x)
        v |= w[(size_t)2 * i * 97 + 1];
    atomicOr(&acc, v);
    __syncthreads();
    if (threadIdx.x == 0) g_is64 = (acc == 0u) ? 1 : 0;
}

__global__ void zero_cnt_kernel() {
    int i = blockIdx.x * blockDim.x + threadIdx.x;
    if (i < N_NODES) g_cnt[i] = 0;
}

// Read index e from edge array (int32, or low word of little-endian int64<2^31)
__device__ __forceinline__ int load_idx(const int* __restrict__ ei, size_t e) {
    return g_is64 ? ei[2 * e] : ei[e];
}

__global__ void hist_kernel(const int* __restrict__ ei) {
    int e = blockIdx.x * blockDim.x + threadIdx.x;
    if (e >= N_EDGES) return;
    int t = load_idx(ei, (size_t)N_EDGES + e);
    atomicAdd(&g_cnt[t], 1);
}

// ---------------------------------------------------------------------------
// Hierarchical exclusive scan of g_cnt -> g_off
// ---------------------------------------------------------------------------
__device__ __forceinline__ int warp_incl_scan(int x) {
#pragma unroll
    for (int d = 1; d < 32; d <<= 1) {
        int y = __shfl_up_sync(0xffffffffu, x, d);
        if ((threadIdx.x & 31) >= d) x += y;
    }
    return x;
}

__global__ void __launch_bounds__(256) scan_local_kernel() {
    int i = blockIdx.x * 256 + threadIdx.x;
    int v = (i < N_NODES) ? g_cnt[i] : 0;
    int lane = threadIdx.x & 31, wid = threadIdx.x >> 5;
    int x = warp_incl_scan(v);
    __shared__ int wsum[8];
    if (lane == 31) wsum[wid] = x;
    __syncthreads();
    if (wid == 0) {
        int s = (lane < 8) ? wsum[lane] : 0;
#pragma unroll
        for (int d = 1; d < 8; d <<= 1) {
            int y = __shfl_up_sync(0xffffffffu, s, d);
            if (lane >= d) s += y;
        }
        if (lane < 8) wsum[lane] = s;
    }
    __syncthreads();
    int incl = x + (wid > 0 ? wsum[wid - 1] : 0);
    if (i < N_NODES) g_off[i] = incl - v;
    if (threadIdx.x == 255) g_bsum[blockIdx.x] = incl;
}

__global__ void __launch_bounds__(256) scan_block_kernel() {
    int t = threadIdx.x;
    int v = (t < NBLK) ? g_bsum[t] : 0;
    int lane = t & 31, wid = t >> 5;
    int x = warp_incl_scan(v);
    __shared__ int wsum[8];
    if (lane == 31) wsum[wid] = x;
    __syncthreads();
    if (wid == 0) {
        int s = (lane < 8) ? wsum[lane] : 0;
#pragma unroll
        for (int d = 1; d < 8; d <<= 1) {
            int y = __shfl_up_sync(0xffffffffu, s, d);
            if (lane >= d) s += y;
        }
        if (lane < 8) wsum[lane] = s;
    }
    __syncthreads();
    int incl = x + (wid > 0 ? wsum[wid - 1] : 0);
    if (t < NBLK) g_bpre[t] = incl - v;
}

__global__ void finalize_kernel() {
    int i = blockIdx.x * blockDim.x + threadIdx.x;
    if (i < N_NODES) {
        int off = g_off[i] + g_bpre[i >> 8];
        g_off[i] = off;
        g_cursor[i] = off;
        g_dis[i] = rsqrtf((float)(g_cnt[i] + 1));   // +1 self-loop
    }
    if (i == 0) g_off[N_NODES] = N_EDGES;
}

// ---------------------------------------------------------------------------
// Fill CSR buckets; per-(edge,batch) coefficients (cC, cD) split per batch.
// ---------------------------------------------------------------------------
__global__ void __launch_bounds__(256)
fill_kernel(const int* __restrict__ ei,
            const float* __restrict__ fdo,
            const float* __restrict__ fluxes) {
    int e = blockIdx.x * blockDim.x + threadIdx.x;
    if (e >= N_EDGES) return;
    int s = load_idx(ei, e);
    int t = load_idx(ei, (size_t)N_EDGES + e);

    int pos = atomicAdd(&g_cursor[t], 1);

    const float f0   = fdo[e];
    const float norm = g_dis[s] * g_dis[t];

    const float k0 = 0.5f * (1.0f + tanhf(fluxes[s] * fluxes[t]));
    const float k1 = 0.5f * (1.0f + tanhf(fluxes[N_NODES + s] * fluxes[N_NODES + t]));
    const float fb0 = k0 * f0 + (1.0f - k0) * (1.0f - f0);
    const float fb1 = k1 * f0 + (1.0f - k1) * (1.0f - f0);

    g_ep0[pos] = make_float2(norm * (1.0f - fb0), norm * fb0);
    g_ep1[pos] = make_float2(norm * (1.0f - fb1), norm * fb1);
    g_esrc[pos] = s;
}

// ---------------------------------------------------------------------------
// Dual GEMM (xc, xd only — NO dependency on degrees; runs on a forked stream)
// ---------------------------------------------------------------------------
__global__ void __launch_bounds__(256)
gemm_kernel(const float* __restrict__ x,
            const float* __restrict__ Wc,
            const float* __restrict__ Wd) {
    const int o  = threadIdx.x >> 2;
    const int kg = threadIdx.x & 3;

    float wc[16], wd[16];
#pragma unroll
    for (int i = 0; i < 16; i++) {
        wc[i] = Wc[o * C + kg * 16 + i];
        wd[i] = Wd[o * C + kg * 16 + i];
    }

    __shared__ __align__(16) float xs[4][C];
    const int M = BATCH * N_NODES;
    const int lr = threadIdx.x >> 6;
    const int lc = threadIdx.x & 63;

    for (int m0 = blockIdx.x * 4; m0 < M; m0 += gridDim.x * 4) {
        __syncthreads();
        xs[lr][lc] = x[(size_t)(m0 + lr) * C + lc];
        __syncthreads();

#pragma unroll
        for (int r2 = 0; r2 < 4; r2++) {
            const float4* xp = (const float4*)&xs[r2][kg * 16];
            float sc = 0.0f, sd = 0.0f;
#pragma unroll
            for (int j = 0; j < 4; j++) {
                float4 xv = xp[j];
                sc = fmaf(wc[4 * j + 0], xv.x, sc);
                sc = fmaf(wc[4 * j + 1], xv.y, sc);
                sc = fmaf(wc[4 * j + 2], xv.z, sc);
                sc = fmaf(wc[4 * j + 3], xv.w, sc);
                sd = fmaf(wd[4 * j + 0], xv.x, sd);
                sd = fmaf(wd[4 * j + 1], xv.y, sd);
                sd = fmaf(wd[4 * j + 2], xv.z, sd);
                sd = fmaf(wd[4 * j + 3], xv.w, sd);
            }
            sc += __shfl_xor_sync(0xffffffffu, sc, 1);
            sc += __shfl_xor_sync(0xffffffffu, sc, 2);
            sd += __shfl_xor_sync(0xffffffffu, sd, 1);
            sd += __shfl_xor_sync(0xffffffffu, sd, 2);

            if (kg == 0) {
                const size_t idx = (size_t)(m0 + r2) * C + o;
                g_xc[idx] = sc;
                g_xd[idx] = sd;
            }
        }
    }
}

// ---------------------------------------------------------------------------
// Gather: one warp per (node, batch); batch-major (all b=0 first) so each
// phase's xc/xd working set (51 MB) stays L2-resident.
// Fused init: acc = bias + (1/deg) * xc[self]   (self-loop, f=0).
// ---------------------------------------------------------------------------
__global__ void __launch_bounds__(256)
gather_kernel(const float* __restrict__ bias, float* __restrict__ out) {
    const int w = (int)((blockIdx.x * blockDim.x + threadIdx.x) >> 5);
    if (w >= BATCH * N_NODES) return;
    const int b    = (w < N_NODES) ? 0 : 1;
    const int n    = (w < N_NODES) ? w : (w - N_NODES);
    const int lane = threadIdx.x & 31;

    const int beg = g_off[n];
    const int end = g_off[n + 1];

    const float*  __restrict__ xcb = g_xc + (size_t)b * N_NODES * C;
    const float*  __restrict__ xdb = g_xd + (size_t)b * N_NODES * C;
    const float2* __restrict__ ep  = b ? g_ep1 : g_ep0;

    // self-loop + bias init
    const float dv = g_dis[n];
    const float nrm = dv * dv;                       // 1/deg
    const float2 bs = *(const float2*)(bias + 2 * lane);
    const float2 xs = *(const float2*)(xcb + (size_t)n * C + 2 * lane);
    float ax = bs.x + nrm * xs.x;
    float ay = bs.y + nrm * xs.y;

    // pipelined bucket loop
    float2 p; int s;
    if (beg < end) { p = ep[beg]; s = g_esrc[beg]; }
    for (int i = beg; i < end; i++) {
        const float2 pc = p;
        const int    sc = s;
        if (i + 1 < end) { p = ep[i + 1]; s = g_esrc[i + 1]; }

        const size_t base = (size_t)sc * C + 2 * lane;
        const float2 a = *(const float2*)(xcb + base);
        const float2 d = *(const float2*)(xdb + base);
        ax = fmaf(pc.x, a.x, fmaf(pc.y, d.x, ax));
        ay = fmaf(pc.x, a.y, fmaf(pc.y, d.y, ay));
    }

    const size_t o = ((size_t)b * N_NODES + n) * C + 2 * lane;
    *(float2*)(out + o) = make_float2(ax, ay);
}

// ---------------------------------------------------------------------------
extern "C" void kernel_launch(void* const* d_in, const int* in_sizes, int n_in,
                              void* d_out, int out_size) {
    const float* x    = (const float*)d_in[0];
    const int*   ei   = (const int*)d_in[1];     // int32 or int64 (sniffed)
    const float* fdo  = (const float*)d_in[2];
    const float* flux = (const float*)d_in[3];
    const float* Wc   = (const float*)d_in[4];
    const float* Wd   = (const float*)d_in[5];
    const float* bias = (const float*)d_in[6];
    float* out = (float*)d_out;

    // one-time host resources (no device allocation; determinism unaffected)
    static cudaStream_t s2 = nullptr;
    static cudaEvent_t evFork = nullptr, evJoin = nullptr;
    if (!s2) {
        cudaStreamCreateWithFlags(&s2, cudaStreamNonBlocking);
        cudaEventCreateWithFlags(&evFork, cudaEventDisableTiming);
        cudaEventCreateWithFlags(&evJoin, cudaEventDisableTiming);
    }

    // Fork: GEMM is independent of the CSR chain — run it concurrently.
    cudaEventRecord(evFork, 0);
    cudaStreamWaitEvent(s2, evFork, 0);
    gemm_kernel<<<2960, 256, 0, s2>>>(x, Wc, Wd);
    cudaEventRecord(evJoin, s2);

    // Main chain: CSR build + per-edge coefficients
    detect_kernel<<<1, 256>>>((const unsigned int*)ei);
    zero_cnt_kernel<<<NBLK, 256>>>();
    hist_kernel<<<(N_EDGES + 255) / 256, 256>>>(ei);
    scan_local_kernel<<<NBLK, 256>>>();
    scan_block_kernel<<<1, 256>>>();
    finalize_kernel<<<NBLK, 256>>>();
    fill_kernel<<<(N_EDGES + 255) / 256, 256>>>(ei, fdo, flux);

    // Join, then gather
    cudaStreamWaitEvent(0, evJoin, 0);
    gather_kernel<<<(BATCH * N_NODES * 32 + 255) / 256, 256>>>(bias, out);
}

// round 4
// speedup vs baseline: 1.2860x; 1.0709x over previous
#include <cuda_runtime.h>
#include <cuda_fp16.h>
#include <math.h>

#define N_NODES 50000
#define N_EDGES 1600000
#define BATCH   2
#define C       64
#define NBLK    ((N_NODES + 255) / 256)

// ---- scratch ----
__device__ int    g_cnt[N_NODES];
__device__ int    g_off[N_NODES + 1];
__device__ int    g_cursor[N_NODES];
__device__ int    g_bsum[NBLK];
__device__ int    g_bpre[NBLK];
__device__ float  g_dis[N_NODES];
__device__ __align__(16) __half g_xch[(size_t)BATCH * N_NODES * C];
__device__ __align__(16) __half g_xdh[(size_t)BATCH * N_NODES * C];
__device__ float2 g_ep0[N_EDGES];
__device__ float2 g_ep1[N_EDGES];
__device__ int    g_esrc[N_EDGES];
__device__ int    g_is64;

// ---- packed f32x2 helpers (Blackwell; ptxas never auto-fuses these) ----
__device__ __forceinline__ unsigned long long pk2(float x, float y) {
    unsigned long long r;
    asm("mov.b64 %0, {%1,%2};" : "=l"(r) : "f"(x), "f"(y));
    return r;
}
__device__ __forceinline__ void upk2(unsigned long long v, float& x, float& y) {
    asm("mov.b64 {%0,%1}, %2;" : "=f"(x), "=f"(y) : "l"(v));
}
__device__ __forceinline__ void fma2(unsigned long long& c,
                                     unsigned long long a,
                                     unsigned long long b) {
    asm("fma.rn.f32x2 %0, %1, %2, %0;" : "+l"(c) : "l"(a), "l"(b));
}

// ---------------------------------------------------------------------------
// detect int64 vs int32 (block 0) + zero g_cnt (all blocks)
// ---------------------------------------------------------------------------
__global__ void detect_zero_kernel(const unsigned int* __restrict__ w) {
    int i = blockIdx.x * blockDim.x + threadIdx.x;
    if (i < N_NODES) g_cnt[i] = 0;
    if (blockIdx.x == 0) {
        __shared__ unsigned int acc;
        if (threadIdx.x == 0) acc = 0u;
        __syncthreads();
        unsigned int v = 0u;
        for (int j = threadIdx.x; j < 4096; j += blockDim.x)
            v |= w[(size_t)2 * j * 97 + 1];
        atomicOr(&acc, v);
        __syncthreads();
        if (threadIdx.x == 0) g_is64 = (acc == 0u) ? 1 : 0;
    }
}

__device__ __forceinline__ int load_idx(const int* __restrict__ ei, size_t e) {
    return g_is64 ? ei[2 * e] : ei[e];
}

__global__ void hist_kernel(const int* __restrict__ ei) {
    int e = blockIdx.x * blockDim.x + threadIdx.x;
    if (e >= N_EDGES) return;
    atomicAdd(&g_cnt[load_idx(ei, (size_t)N_EDGES + e)], 1);
}

// ---------------------------------------------------------------------------
// hierarchical exclusive scan
// ---------------------------------------------------------------------------
__device__ __forceinline__ int warp_incl_scan(int x) {
#pragma unroll
    for (int d = 1; d < 32; d <<= 1) {
        int y = __shfl_up_sync(0xffffffffu, x, d);
        if ((threadIdx.x & 31) >= d) x += y;
    }
    return x;
}

__global__ void __launch_bounds__(256) scan_local_kernel() {
    int i = blockIdx.x * 256 + threadIdx.x;
    int v = (i < N_NODES) ? g_cnt[i] : 0;
    int lane = threadIdx.x & 31, wid = threadIdx.x >> 5;
    int x = warp_incl_scan(v);
    __shared__ int wsum[8];
    if (lane == 31) wsum[wid] = x;
    __syncthreads();
    if (wid == 0) {
        int s = (lane < 8) ? wsum[lane] : 0;
#pragma unroll
        for (int d = 1; d < 8; d <<= 1) {
            int y = __shfl_up_sync(0xffffffffu, s, d);
            if (lane >= d) s += y;
        }
        if (lane < 8) wsum[lane] = s;
    }
    __syncthreads();
    int incl = x + (wid > 0 ? wsum[wid - 1] : 0);
    if (i < N_NODES) g_off[i] = incl - v;
    if (threadIdx.x == 255) g_bsum[blockIdx.x] = incl;
}

__global__ void __launch_bounds__(256) scan_block_kernel() {
    int t = threadIdx.x;
    int v = (t < NBLK) ? g_bsum[t] : 0;
    int lane = t & 31, wid = t >> 5;
    int x = warp_incl_scan(v);
    __shared__ int wsum[8];
    if (lane == 31) wsum[wid] = x;
    __syncthreads();
    if (wid == 0) {
        int s = (lane < 8) ? wsum[lane] : 0;
#pragma unroll
        for (int d = 1; d < 8; d <<= 1) {
            int y = __shfl_up_sync(0xffffffffu, s, d);
            if (lane >= d) s += y;
        }
        if (lane < 8) wsum[lane] = s;
    }
    __syncthreads();
    int incl = x + (wid > 0 ? wsum[wid - 1] : 0);
    if (t < NBLK) g_bpre[t] = incl - v;
}

__global__ void finalize_kernel() {
    int i = blockIdx.x * blockDim.x + threadIdx.x;
    if (i < N_NODES) {
        int off = g_off[i] + g_bpre[i >> 8];
        g_off[i] = off;
        g_cursor[i] = off;
        g_dis[i] = rsqrtf((float)(g_cnt[i] + 1));
    }
    if (i == 0) g_off[N_NODES] = N_EDGES;
}

// ---------------------------------------------------------------------------
// fill CSR buckets with per-(edge,batch) coefficients
// ---------------------------------------------------------------------------
__global__ void __launch_bounds__(256)
fill_kernel(const int* __restrict__ ei,
            const float* __restrict__ fdo,
            const float* __restrict__ fluxes) {
    int e = blockIdx.x * blockDim.x + threadIdx.x;
    if (e >= N_EDGES) return;
    int s = load_idx(ei, e);
    int t = load_idx(ei, (size_t)N_EDGES + e);

    int pos = atomicAdd(&g_cursor[t], 1);

    const float f0   = fdo[e];
    const float norm = g_dis[s] * g_dis[t];

    const float k0 = 0.5f * (1.0f + tanhf(fluxes[s] * fluxes[t]));
    const float k1 = 0.5f * (1.0f + tanhf(fluxes[N_NODES + s] * fluxes[N_NODES + t]));
    const float fb0 = k0 * f0 + (1.0f - k0) * (1.0f - f0);
    const float fb1 = k1 * f0 + (1.0f - k1) * (1.0f - f0);

    g_ep0[pos] = make_float2(norm * (1.0f - fb0), norm * fb0);
    g_ep1[pos] = make_float2(norm * (1.0f - fb1), norm * fb1);
    g_esrc[pos] = s;
}

// ---------------------------------------------------------------------------
// Dual GEMM -> fp16 xc/xd. Packed f32x2 FFMA2: acc=(sc,sd), w=(wc_k,wd_k).
// Thread (o = tid>>2, kg = tid&3): 16-wide K slice for channel o, both mats.
// Reduce over kg via shfl_xor 1,2; pair-exchange via shfl_xor 4 -> half2 store.
// Runs on a forked stream, overlapping the CSR chain.
// ---------------------------------------------------------------------------
__global__ void __launch_bounds__(256)
gemm_kernel(const float* __restrict__ x,
            const float* __restrict__ Wc,
            const float* __restrict__ Wd) {
    const int o  = threadIdx.x >> 2;
    const int kg = threadIdx.x & 3;

    unsigned long long wp[16];
#pragma unroll
    for (int i = 0; i < 16; i++)
        wp[i] = pk2(Wc[o * C + kg * 16 + i], Wd[o * C + kg * 16 + i]);

    __shared__ __align__(16) float xs[4][C];
    const int M = BATCH * N_NODES;
    const int lr = threadIdx.x >> 6;
    const int lc = threadIdx.x & 63;

    for (int m0 = blockIdx.x * 4; m0 < M; m0 += gridDim.x * 4) {
        __syncthreads();
        xs[lr][lc] = x[(size_t)(m0 + lr) * C + lc];
        __syncthreads();

#pragma unroll
        for (int r2 = 0; r2 < 4; r2++) {
            const float4* xp = (const float4*)&xs[r2][kg * 16];
            unsigned long long acc = 0ull;   // (sc, sd) — 0.0f bits
#pragma unroll
            for (int j = 0; j < 4; j++) {
                float4 xv = xp[j];
                fma2(acc, pk2(xv.x, xv.x), wp[4 * j + 0]);
                fma2(acc, pk2(xv.y, xv.y), wp[4 * j + 1]);
                fma2(acc, pk2(xv.z, xv.z), wp[4 * j + 2]);
                fma2(acc, pk2(xv.w, xv.w), wp[4 * j + 3]);
            }
            float sc, sd;
            upk2(acc, sc, sd);
            sc += __shfl_xor_sync(0xffffffffu, sc, 1);
            sc += __shfl_xor_sync(0xffffffffu, sc, 2);
            sd += __shfl_xor_sync(0xffffffffu, sd, 1);
            sd += __shfl_xor_sync(0xffffffffu, sd, 2);
            // lanes now uniform within kg-quad; grab the odd/even partner channel
            float sc2 = __shfl_xor_sync(0xffffffffu, sc, 4);
            float sd2 = __shfl_xor_sync(0xffffffffu, sd, 4);

            if (kg == 0 && (o & 1) == 0) {   // even channel lane writes the pair
                const size_t idx = (size_t)(m0 + r2) * C + o;
                *(__half2*)(g_xch + idx) = __floats2half2_rn(sc, sc2);
                *(__half2*)(g_xdh + idx) = __floats2half2_rn(sd, sd2);
            }
        }
    }
}

// ---------------------------------------------------------------------------
// Gather: one warp per (node,batch), batch-major. Two half-warps process two
// edges per iteration; each lane covers 4 channels (fp16 rows, 128B/row).
// ---------------------------------------------------------------------------
__global__ void __launch_bounds__(256)
gather_kernel(const float* __restrict__ bias, float* __restrict__ out) {
    const int w = (int)((blockIdx.x * blockDim.x + threadIdx.x) >> 5);
    if (w >= BATCH * N_NODES) return;
    const int b    = (w < N_NODES) ? 0 : 1;
    const int n    = (w < N_NODES) ? w : (w - N_NODES);
    const int lane = threadIdx.x & 31;
    const int hw   = lane >> 4;          // half-warp id
    const int ch   = (lane & 15) << 2;   // 4 channels per lane

    const int beg = g_off[n];
    const int end = g_off[n + 1];

    const __half*  __restrict__ xcb = g_xch + (size_t)b * N_NODES * C;
    const __half*  __restrict__ xdb = g_xdh + (size_t)b * N_NODES * C;
    const float2*  __restrict__ ep  = b ? g_ep1 : g_ep0;

    unsigned long long a01 = 0ull, a23 = 0ull;   // fp32 pair accumulators

    if (hw == 0) {   // self-loop + bias init in half-warp 0
        const float dv  = g_dis[n];
        const float nrm = dv * dv;
        const float4 bs = *(const float4*)(bias + ch);
        const uint2 xh  = *(const uint2*)(xcb + (size_t)n * C + ch);
        const float2 x0 = __half22float2(*(const __half2*)&xh.x);
        const float2 x1 = __half22float2(*(const __half2*)&xh.y);
        a01 = pk2(fmaf(nrm, x0.x, bs.x), fmaf(nrm, x0.y, bs.y));
        a23 = pk2(fmaf(nrm, x1.x, bs.z), fmaf(nrm, x1.y, bs.w));
    }

    for (int i = beg + hw; i < end; i += 2) {
        const int    s  = g_esrc[i];
        const float2 cf = ep[i];
        const size_t base = (size_t)s * C + ch;
        const uint2 ah = *(const uint2*)(xcb + base);
        const uint2 dh = *(const uint2*)(xdb + base);

        const unsigned long long cc = pk2(cf.x, cf.x);
        const unsigned long long cd = pk2(cf.y, cf.y);

        const float2 a0 = __half22float2(*(const __half2*)&ah.x);
        const float2 a1 = __half22float2(*(const __half2*)&ah.y);
        const float2 d0 = __half22float2(*(const __half2*)&dh.x);
        const float2 d1 = __half22float2(*(const __half2*)&dh.y);

        fma2(a01, pk2(a0.x, a0.y), cc);
        fma2(a23, pk2(a1.x, a1.y), cc);
        fma2(a01, pk2(d0.x, d0.y), cd);
        fma2(a23, pk2(d1.x, d1.y), cd);
    }

    float f0, f1, f2, f3;
    upk2(a01, f0, f1);
    upk2(a23, f2, f3);
    f0 += __shfl_xor_sync(0xffffffffu, f0, 16);
    f1 += __shfl_xor_sync(0xffffffffu, f1, 16);
    f2 += __shfl_xor_sync(0xffffffffu, f2, 16);
    f3 += __shfl_xor_sync(0xffffffffu, f3, 16);

    if (hw == 0)
        *(float4*)(out + ((size_t)b * N_NODES + n) * C + ch) =
            make_float4(f0, f1, f2, f3);
}

// ---------------------------------------------------------------------------
extern "C" void kernel_launch(void* const* d_in, const int* in_sizes, int n_in,
                              void* d_out, int out_size) {
    const float* x    = (const float*)d_in[0];
    const int*   ei   = (const int*)d_in[1];
    const float* fdo  = (const float*)d_in[2];
    const float* flux = (const float*)d_in[3];
    const float* Wc   = (const float*)d_in[4];
    const float* Wd   = (const float*)d_in[5];
    const float* bias = (const float*)d_in[6];
    float* out = (float*)d_out;

    static cudaStream_t s2 = nullptr;
    static cudaEvent_t evFork = nullptr, evJoin = nullptr;
    if (!s2) {
        cudaStreamCreateWithFlags(&s2, cudaStreamNonBlocking);
        cudaEventCreateWithFlags(&evFork, cudaEventDisableTiming);
        cudaEventCreateWithFlags(&evJoin, cudaEventDisableTiming);
    }

    // fork: GEMM concurrent with CSR chain
    cudaEventRecord(evFork, 0);
    cudaStreamWaitEvent(s2, evFork, 0);
    gemm_kernel<<<2960, 256, 0, s2>>>(x, Wc, Wd);
    cudaEventRecord(evJoin, s2);

    detect_zero_kernel<<<NBLK, 256>>>((const unsigned int*)ei);
    hist_kernel<<<(N_EDGES + 255) / 256, 256>>>(ei);
    scan_local_kernel<<<NBLK, 256>>>();
    scan_block_kernel<<<1, 256>>>();
    finalize_kernel<<<NBLK, 256>>>();
    fill_kernel<<<(N_EDGES + 255) / 256, 256>>>(ei, fdo, flux);

    cudaStreamWaitEvent(0, evJoin, 0);
    gather_kernel<<<(BATCH * N_NODES * 32 + 255) / 256, 256>>>(bias, out);
}

// round 5
// speedup vs baseline: 1.3195x; 1.0261x over previous
#include <cuda_runtime.h>
#include <cuda_fp16.h>
#include <math.h>

#define N_NODES 50000
#define N_EDGES 1600000
#define BATCH   2
#define C       64
#define NBLK    ((N_NODES + 255) / 256)

// ---- scratch ----
__device__ int    g_cnt[N_NODES];
__device__ int    g_off[N_NODES + 1];
__device__ int    g_cursor[N_NODES];
__device__ int    g_bsum[NBLK];
__device__ int    g_bpre[NBLK];
__device__ float  g_dis[N_NODES];
// interleaved per (batch,node) row: [xc: 64 halfs][xd: 64 halfs] = 256 B
__device__ __align__(16) __half g_xi[(size_t)BATCH * N_NODES * 2 * C];
__device__ float2 g_ep0[N_EDGES];
__device__ float2 g_ep1[N_EDGES];
__device__ int    g_esrc[N_EDGES];
__device__ int    g_is64;

// ---- packed f32x2 helpers ----
__device__ __forceinline__ unsigned long long pk2(float x, float y) {
    unsigned long long r;
    asm("mov.b64 %0, {%1,%2};" : "=l"(r) : "f"(x), "f"(y));
    return r;
}
__device__ __forceinline__ void upk2(unsigned long long v, float& x, float& y) {
    asm("mov.b64 {%0,%1}, %2;" : "=f"(x), "=f"(y) : "l"(v));
}
__device__ __forceinline__ void fma2(unsigned long long& c,
                                     unsigned long long a,
                                     unsigned long long b) {
    asm("fma.rn.f32x2 %0, %1, %2, %0;" : "+l"(c) : "l"(a), "l"(b));
}

// ---------------------------------------------------------------------------
__global__ void detect_zero_kernel(const unsigned int* __restrict__ w) {
    int i = blockIdx.x * blockDim.x + threadIdx.x;
    if (i < N_NODES) g_cnt[i] = 0;
    if (blockIdx.x == 0) {
        __shared__ unsigned int acc;
        if (threadIdx.x == 0) acc = 0u;
        __syncthreads();
        unsigned int v = 0u;
        for (int j = threadIdx.x; j < 4096; j += blockDim.x)
            v |= w[(size_t)2 * j * 97 + 1];
        atomicOr(&acc, v);
        __syncthreads();
        if (threadIdx.x == 0) g_is64 = (acc == 0u) ? 1 : 0;
    }
}

__device__ __forceinline__ int load_idx(const int* __restrict__ ei, size_t e) {
    return g_is64 ? ei[2 * e] : ei[e];
}

__global__ void hist_kernel(const int* __restrict__ ei) {
    int e = blockIdx.x * blockDim.x + threadIdx.x;
    if (e >= N_EDGES) return;
    atomicAdd(&g_cnt[load_idx(ei, (size_t)N_EDGES + e)], 1);
}

// ---------------------------------------------------------------------------
__device__ __forceinline__ int warp_incl_scan(int x) {
#pragma unroll
    for (int d = 1; d < 32; d <<= 1) {
        int y = __shfl_up_sync(0xffffffffu, x, d);
        if ((threadIdx.x & 31) >= d) x += y;
    }
    return x;
}

__global__ void __launch_bounds__(256) scan_local_kernel() {
    int i = blockIdx.x * 256 + threadIdx.x;
    int v = (i < N_NODES) ? g_cnt[i] : 0;
    int lane = threadIdx.x & 31, wid = threadIdx.x >> 5;
    int x = warp_incl_scan(v);
    __shared__ int wsum[8];
    if (lane == 31) wsum[wid] = x;
    __syncthreads();
    if (wid == 0) {
        int s = (lane < 8) ? wsum[lane] : 0;
#pragma unroll
        for (int d = 1; d < 8; d <<= 1) {
            int y = __shfl_up_sync(0xffffffffu, s, d);
            if (lane >= d) s += y;
        }
        if (lane < 8) wsum[lane] = s;
    }
    __syncthreads();
    int incl = x + (wid > 0 ? wsum[wid - 1] : 0);
    if (i < N_NODES) g_off[i] = incl - v;
    if (threadIdx.x == 255) g_bsum[blockIdx.x] = incl;
}

__global__ void __launch_bounds__(256) scan_block_kernel() {
    int t = threadIdx.x;
    int v = (t < NBLK) ? g_bsum[t] : 0;
    int lane = t & 31, wid = t >> 5;
    int x = warp_incl_scan(v);
    __shared__ int wsum[8];
    if (lane == 31) wsum[wid] = x;
    __syncthreads();
    if (wid == 0) {
        int s = (lane < 8) ? wsum[lane] : 0;
#pragma unroll
        for (int d = 1; d < 8; d <<= 1) {
            int y = __shfl_up_sync(0xffffffffu, s, d);
            if (lane >= d) s += y;
        }
        if (lane < 8) wsum[lane] = s;
    }
    __syncthreads();
    int incl = x + (wid > 0 ? wsum[wid - 1] : 0);
    if (t < NBLK) g_bpre[t] = incl - v;
}

__global__ void finalize_kernel() {
    int i = blockIdx.x * blockDim.x + threadIdx.x;
    if (i < N_NODES) {
        int off = g_off[i] + g_bpre[i >> 8];
        g_off[i] = off;
        g_cursor[i] = off;
        g_dis[i] = rsqrtf((float)(g_cnt[i] + 1));
    }
    if (i == 0) g_off[N_NODES] = N_EDGES;
}

// ---------------------------------------------------------------------------
__global__ void __launch_bounds__(256)
fill_kernel(const int* __restrict__ ei,
            const float* __restrict__ fdo,
            const float* __restrict__ fluxes) {
    int e = blockIdx.x * blockDim.x + threadIdx.x;
    if (e >= N_EDGES) return;
    int s = load_idx(ei, e);
    int t = load_idx(ei, (size_t)N_EDGES + e);

    int pos = atomicAdd(&g_cursor[t], 1);

    const float f0   = fdo[e];
    const float norm = g_dis[s] * g_dis[t];

    const float k0 = 0.5f * (1.0f + tanhf(fluxes[s] * fluxes[t]));
    const float k1 = 0.5f * (1.0f + tanhf(fluxes[N_NODES + s] * fluxes[N_NODES + t]));
    const float fb0 = k0 * f0 + (1.0f - k0) * (1.0f - f0);
    const float fb1 = k1 * f0 + (1.0f - k1) * (1.0f - f0);

    g_ep0[pos] = make_float2(norm * (1.0f - fb0), norm * fb0);
    g_ep1[pos] = make_float2(norm * (1.0f - fb1), norm * fb1);
    g_esrc[pos] = s;
}

// ---------------------------------------------------------------------------
// Dual GEMM -> interleaved fp16 rows [xc(64)|xd(64)]. FFMA2-packed.
// ---------------------------------------------------------------------------
__global__ void __launch_bounds__(256)
gemm_kernel(const float* __restrict__ x,
            const float* __restrict__ Wc,
            const float* __restrict__ Wd) {
    const int o  = threadIdx.x >> 2;
    const int kg = threadIdx.x & 3;

    unsigned long long wp[16];
#pragma unroll
    for (int i = 0; i < 16; i++)
        wp[i] = pk2(Wc[o * C + kg * 16 + i], Wd[o * C + kg * 16 + i]);

    __shared__ __align__(16) float xs[4][C];
    const int M = BATCH * N_NODES;
    const int lr = threadIdx.x >> 6;
    const int lc = threadIdx.x & 63;

    for (int m0 = blockIdx.x * 4; m0 < M; m0 += gridDim.x * 4) {
        __syncthreads();
        xs[lr][lc] = x[(size_t)(m0 + lr) * C + lc];
        __syncthreads();

#pragma unroll
        for (int r2 = 0; r2 < 4; r2++) {
            const float4* xp = (const float4*)&xs[r2][kg * 16];
            unsigned long long acc = 0ull;
#pragma unroll
            for (int j = 0; j < 4; j++) {
                float4 xv = xp[j];
                fma2(acc, pk2(xv.x, xv.x), wp[4 * j + 0]);
                fma2(acc, pk2(xv.y, xv.y), wp[4 * j + 1]);
                fma2(acc, pk2(xv.z, xv.z), wp[4 * j + 2]);
                fma2(acc, pk2(xv.w, xv.w), wp[4 * j + 3]);
            }
            float sc, sd;
            upk2(acc, sc, sd);
            sc += __shfl_xor_sync(0xffffffffu, sc, 1);
            sc += __shfl_xor_sync(0xffffffffu, sc, 2);
            sd += __shfl_xor_sync(0xffffffffu, sd, 1);
            sd += __shfl_xor_sync(0xffffffffu, sd, 2);
            float sc2 = __shfl_xor_sync(0xffffffffu, sc, 4);
            float sd2 = __shfl_xor_sync(0xffffffffu, sd, 4);

            if (kg == 0 && (o & 1) == 0) {
                __half* row = g_xi + (size_t)(m0 + r2) * (2 * C);
                *(__half2*)(row + o)     = __floats2half2_rn(sc, sc2);
                *(__half2*)(row + C + o) = __floats2half2_rn(sd, sd2);
            }
        }
    }
}

// ---------------------------------------------------------------------------
// Gather: one warp per (node,batch), batch-major. Four 8-lane groups each
// process one edge per iteration (4 edges/warp/iter); lane covers 8 channels
// (2 x uint4 fp16). esrc/ep software-pipelined one iteration ahead.
// Cross-group reduce via shfl_xor 8,16; lanes 0-7 store the 256 B row.
// ---------------------------------------------------------------------------
__global__ void __launch_bounds__(256)
gather_kernel(const float* __restrict__ bias, float* __restrict__ out) {
    const int w = (int)((blockIdx.x * blockDim.x + threadIdx.x) >> 5);
    if (w >= BATCH * N_NODES) return;
    const int b    = (w < N_NODES) ? 0 : 1;
    const int n    = (w < N_NODES) ? w : (w - N_NODES);
    const int lane = threadIdx.x & 31;
    const int g    = lane >> 3;        // edge group 0..3
    const int l8   = lane & 7;         // 8 channels: l8*8 .. +8

    const int beg = g_off[n];
    const int end = g_off[n + 1];

    const __half*  __restrict__ xib = g_xi + (size_t)b * N_NODES * (2 * C);
    const float2*  __restrict__ ep  = b ? g_ep1 : g_ep0;

    unsigned long long a0 = 0ull, a1 = 0ull, a2 = 0ull, a3 = 0ull;

    if (g == 0) {   // self-loop + bias init
        const float dv  = g_dis[n];
        const float nrm = dv * dv;
        const float4 b0 = *(const float4*)(bias + l8 * 8);
        const float4 b1 = *(const float4*)(bias + l8 * 8 + 4);
        const uint4  xh = *(const uint4*)(xib + (size_t)n * (2 * C) + l8 * 8);
        const float2 x0 = __half22float2(*(const __half2*)&xh.x);
        const float2 x1 = __half22float2(*(const __half2*)&xh.y);
        const float2 x2 = __half22float2(*(const __half2*)&xh.z);
        const float2 x3 = __half22float2(*(const __half2*)&xh.w);
        a0 = pk2(fmaf(nrm, x0.x, b0.x), fmaf(nrm, x0.y, b0.y));
        a1 = pk2(fmaf(nrm, x1.x, b0.z), fmaf(nrm, x1.y, b0.w));
        a2 = pk2(fmaf(nrm, x2.x, b1.x), fmaf(nrm, x2.y, b1.y));
        a3 = pk2(fmaf(nrm, x3.x, b1.z), fmaf(nrm, x3.y, b1.w));
    }

    int i = beg + g;
    if (i < end) {
        int    s  = g_esrc[i];
        float2 cf = ep[i];
        for (; i < end; ) {
            const int inext = i + 4;
            int    s2  = 0;
            float2 cf2 = make_float2(0.0f, 0.0f);
            if (inext < end) { s2 = g_esrc[inext]; cf2 = ep[inext]; }

            const __half* row = xib + (size_t)s * (2 * C) + l8 * 8;
            const uint4 A = *(const uint4*)(row);        // xc: 8 halfs
            const uint4 D = *(const uint4*)(row + C);    // xd: 8 halfs

            const unsigned long long cc = pk2(cf.x, cf.x);
            const unsigned long long cd = pk2(cf.y, cf.y);

            float2 t;
            t = __half22float2(*(const __half2*)&A.x); fma2(a0, pk2(t.x, t.y), cc);
            t = __half22float2(*(const __half2*)&A.y); fma2(a1, pk2(t.x, t.y), cc);
            t = __half22float2(*(const __half2*)&A.z); fma2(a2, pk2(t.x, t.y), cc);
            t = __half22float2(*(const __half2*)&A.w); fma2(a3, pk2(t.x, t.y), cc);
            t = __half22float2(*(const __half2*)&D.x); fma2(a0, pk2(t.x, t.y), cd);
            t = __half22float2(*(const __half2*)&D.y); fma2(a1, pk2(t.x, t.y), cd);
            t = __half22float2(*(const __half2*)&D.z); fma2(a2, pk2(t.x, t.y), cd);
            t = __half22float2(*(const __half2*)&D.w); fma2(a3, pk2(t.x, t.y), cd);

            i = inext; s = s2; cf = cf2;
        }
    }

    // reduce the 4 groups
    float f0, f1, f2, f3, f4, f5, f6, f7;
    upk2(a0, f0, f1); upk2(a1, f2, f3); upk2(a2, f4, f5); upk2(a3, f6, f7);
#pragma unroll
    for (int d = 8; d <= 16; d <<= 1) {
        f0 += __shfl_xor_sync(0xffffffffu, f0, d);
        f1 += __shfl_xor_sync(0xffffffffu, f1, d);
        f2 += __shfl_xor_sync(0xffffffffu, f2, d);
        f3 += __shfl_xor_sync(0xffffffffu, f3, d);
        f4 += __shfl_xor_sync(0xffffffffu, f4, d);
        f5 += __shfl_xor_sync(0xffffffffu, f5, d);
        f6 += __shfl_xor_sync(0xffffffffu, f6, d);
        f7 += __shfl_xor_sync(0xffffffffu, f7, d);
    }

    if (g == 0) {
        float* orow = out + ((size_t)b * N_NODES + n) * C + l8 * 8;
        *(float4*)(orow)     = make_float4(f0, f1, f2, f3);
        *(float4*)(orow + 4) = make_float4(f4, f5, f6, f7);
    }
}

// ---------------------------------------------------------------------------
extern "C" void kernel_launch(void* const* d_in, const int* in_sizes, int n_in,
                              void* d_out, int out_size) {
    const float* x    = (const float*)d_in[0];
    const int*   ei   = (const int*)d_in[1];
    const float* fdo  = (const float*)d_in[2];
    const float* flux = (const float*)d_in[3];
    const float* Wc   = (const float*)d_in[4];
    const float* Wd   = (const float*)d_in[5];
    const float* bias = (const float*)d_in[6];
    float* out = (float*)d_out;

    static cudaStream_t s2 = nullptr;
    static cudaEvent_t evFork = nullptr, evJoin = nullptr;
    if (!s2) {
        cudaStreamCreateWithFlags(&s2, cudaStreamNonBlocking);
        cudaEventCreateWithFlags(&evFork, cudaEventDisableTiming);
        cudaEventCreateWithFlags(&evJoin, cudaEventDisableTiming);
    }

    cudaEventRecord(evFork, 0);
    cudaStreamWaitEvent(s2, evFork, 0);
    gemm_kernel<<<2960, 256, 0, s2>>>(x, Wc, Wd);
    cudaEventRecord(evJoin, s2);

    detect_zero_kernel<<<NBLK, 256>>>((const unsigned int*)ei);
    hist_kernel<<<(N_EDGES + 255) / 256, 256>>>(ei);
    scan_local_kernel<<<NBLK, 256>>>();
    scan_block_kernel<<<1, 256>>>();
    finalize_kernel<<<NBLK, 256>>>();
    fill_kernel<<<(N_EDGES + 255) / 256, 256>>>(ei, fdo, flux);

    cudaStreamWaitEvent(0, evJoin, 0);
    gather_kernel<<<(BATCH * N_NODES * 32 + 255) / 256, 256>>>(bias, out);
}